// round 3
// baseline (speedup 1.0000x reference)
#include <cuda_runtime.h>

// Problem constants (fixed by setup_inputs)
#define BB  2
#define CC  32
#define TT  64
#define HH  64
#define WW  64
#define HWSZ 4096          // H*W
#define NN  512
#define CF  32
#define CHN 16
#define FT  400            // featT == orgt == 400
#define LL  (FT*NN)        // 204800
#define BL  (BB*LL)        // 409600
#define NBLK_H (BB*FT)     // 800
#define T_SCALE (63.0f/399.0f)
#define EPS 1e-5f

// Scratch (static device allocations; no cudaMalloc allowed)
__device__ float g_xg[BB*CC*TT*NN];     // gathered x:  [b][c][t][n]   8 MB
__device__ float g_h [BB*CHN*LL];       // pre-BN h:    [b][o][t*N+n] 26 MB
__device__ float g_r [BB*TT*HWSZ];      // Wr@x head:   [b][t][hw]     2 MB
__device__ float g_W1f[CHN*CF];
__device__ float g_b1f[CHN];
__device__ float g_part[NBLK_H*32];     // per-block partial sums (16 sum + 16 sumsq)
__device__ float g_stats[32];

// ---------------------------------------------------------------------------
// K0: fuse W1@Wf -> W1f, W1@bf + b1 -> b1f.  One block, 512 threads.
__global__ void k_prep(const float* __restrict__ W1, const float* __restrict__ b1,
                       const float* __restrict__ Wf, const float* __restrict__ bf) {
    int t = threadIdx.x;                // 0..511
    int o = t >> 5, c = t & 31;
    float acc = 0.f;
#pragma unroll
    for (int k = 0; k < CF; ++k) acc += W1[o*CF + k] * Wf[k*CC + c];
    g_W1f[o*CF + c] = acc;
    if (t < CHN) {
        float a = b1[t];
#pragma unroll
        for (int k = 0; k < CF; ++k) a += W1[t*CF + k] * bf[k];
        g_b1f[t] = a;
    }
}

// ---------------------------------------------------------------------------
// K1: r[b][t][hw] = sum_c Wr[c]*x[b][c][t][hw] + br   (full read of x: 67MB)
__global__ void k_r(const float* __restrict__ x, const float* __restrict__ Wr,
                    const float* __restrict__ br) {
    int gid = blockIdx.x * blockDim.x + threadIdx.x;     // < B*T*HW = 524288
    int hw = gid & (HWSZ-1);
    int bt = gid >> 12;                                  // b*T + t
    int b  = bt >> 6, t = bt & 63;
    const float* xp = x + ((size_t)b*CC*TT + t)*HWSZ + hw;
    float acc = __ldg(br);
#pragma unroll
    for (int c = 0; c < CC; ++c)
        acc += __ldg(Wr + c) * xp[(size_t)c*TT*HWSZ];
    g_r[gid] = acc;
}

// ---------------------------------------------------------------------------
// K2: gather xg[b][c][t][n] = x[b][c][t][coordH*W + coordW]
__global__ void k_gather(const float* __restrict__ x, const int* __restrict__ coord) {
    int gid = blockIdx.x * blockDim.x + threadIdx.x;     // < B*C*T*N = 2097152
    int n = gid & (NN-1);
    int t = (gid >> 9) & 63;
    int c = (gid >> 15) & 31;
    int b = gid >> 20;
    int ch = __ldg(coord + ((size_t)(b*NN + n))*2);
    int cw = __ldg(coord + ((size_t)(b*NN + n))*2 + 1);
    g_xg[gid] = x[(((size_t)(b*CC + c))*TT + t)*HWSZ + ch*WW + cw];
}

// ---------------------------------------------------------------------------
// K3: h[b][o][t*N+n] = W1f @ lerp_t(xg) + b1f ; per-block partial sum/sumsq.
// grid = B*FT (800), block = 512 (n)
__global__ void k_h() {
    __shared__ float sW[CHN*CF];
    __shared__ float sb[CHN];
    __shared__ float redS[CHN][16];
    __shared__ float redQ[CHN][16];

    int tid = threadIdx.x;
    if (tid < CHN*CF) sW[tid] = g_W1f[tid];
    if (tid < CHN)    sb[tid] = g_b1f[tid];

    int bt = blockIdx.x;
    int b = bt / FT, t = bt - b*FT;
    float pos = (float)t * T_SCALE;
    int i0 = (int)floorf(pos);
    float w = pos - (float)i0;
    int i1 = min(i0 + 1, TT - 1);
    __syncthreads();

    int n = tid;
    const float* p0 = g_xg + ((size_t)b*CC*TT + i0)*NN + n;
    const float* p1 = g_xg + ((size_t)b*CC*TT + i1)*NN + n;

    float hv[CHN];
#pragma unroll
    for (int o = 0; o < CHN; ++o) hv[o] = sb[o];
#pragma unroll
    for (int c = 0; c < CC; ++c) {
        float a = p0[(size_t)c*TT*NN];
        float bq = p1[(size_t)c*TT*NN];
        float xi = a + (bq - a) * w;
#pragma unroll
        for (int o = 0; o < CHN; ++o) hv[o] += sW[o*CF + c] * xi;
    }

    float* hp = g_h + (size_t)b*CHN*LL + (size_t)t*NN + n;
    int warp = tid >> 5, lane = tid & 31;
#pragma unroll
    for (int o = 0; o < CHN; ++o) {
        hp[(size_t)o*LL] = hv[o];
        float v = hv[o], q = hv[o]*hv[o];
#pragma unroll
        for (int off = 16; off; off >>= 1) {
            v += __shfl_down_sync(0xffffffffu, v, off);
            q += __shfl_down_sync(0xffffffffu, q, off);
        }
        if (lane == 0) { redS[o][warp] = v; redQ[o][warp] = q; }
    }
    __syncthreads();
    if (tid < 32) {
        int o = tid & 15;
        bool sq = tid >= 16;
        float a = 0.f;
#pragma unroll
        for (int wp = 0; wp < 16; ++wp)
            a += sq ? redQ[o][wp] : redS[o][wp];
        g_part[blockIdx.x*32 + tid] = a;
    }
}

// ---------------------------------------------------------------------------
// K3b: deterministic reduction of 800 partials -> g_stats[32]
__global__ void k_redstats() {
    __shared__ float sm[256];
    int s = blockIdx.x;                 // 0..31
    float a = 0.f;
    for (int i = threadIdx.x; i < NBLK_H; i += 256)
        a += g_part[i*32 + s];
    sm[threadIdx.x] = a;
    __syncthreads();
    for (int off = 128; off; off >>= 1) {
        if (threadIdx.x < off) sm[threadIdx.x] += sm[threadIdx.x + off];
        __syncthreads();
    }
    if (threadIdx.x == 0) g_stats[s] = sm[0];
}

// ---------------------------------------------------------------------------
// K4: out = W2 @ relu(BN(h)) + b2
// grid = BL/256 (1600), block = 256; thread per (b,l)
__global__ void k_out(const float* __restrict__ gamma, const float* __restrict__ beta,
                      const float* __restrict__ W2, const float* __restrict__ b2,
                      float* __restrict__ out) {
    __shared__ float sW2[CHN*CHN];
    __shared__ float sb2[CHN];
    __shared__ float sScale[CHN];
    __shared__ float sShift[CHN];
    int tid = threadIdx.x;
    if (tid < CHN*CHN) sW2[tid] = W2[tid];
    if (tid < CHN) {
        sb2[tid] = b2[tid];
        float mu  = g_stats[tid] / (float)BL;
        float var = g_stats[16 + tid] / (float)BL - mu*mu;
        float inv = rsqrtf(var + EPS);
        float sc  = gamma[tid] * inv;
        sScale[tid] = sc;
        sShift[tid] = beta[tid] - mu*sc;
    }
    __syncthreads();

    int gid = blockIdx.x * blockDim.x + tid;     // < BL
    int b = gid / LL;
    int l = gid - b*LL;
    const float* hp = g_h + (size_t)b*CHN*LL + l;
    float v[CHN];
#pragma unroll
    for (int o = 0; o < CHN; ++o)
        v[o] = fmaxf(hp[(size_t)o*LL] * sScale[o] + sShift[o], 0.f);
    float* op = out + (size_t)b*CHN*LL + l;
#pragma unroll
    for (int o2 = 0; o2 < CHN; ++o2) {
        float a = sb2[o2];
#pragma unroll
        for (int o = 0; o < CHN; ++o) a += sW2[o2*CHN + o] * v[o];
        op[(size_t)o2*LL] = a;
    }
}

// ---------------------------------------------------------------------------
// K5: result[b][0][t][hw] = lerp_t(r)     (t: 64 -> 400)
__global__ void k_result(float* __restrict__ outR) {
    int gid = blockIdx.x * blockDim.x + threadIdx.x;     // < B*FT*HW = 3276800
    int hw = gid & (HWSZ-1);
    int bt = gid >> 12;                                  // b*FT + t
    int b = bt / FT, t = bt - b*FT;
    float pos = (float)t * T_SCALE;
    int i0 = (int)floorf(pos);
    float w = pos - (float)i0;
    int i1 = min(i0 + 1, TT - 1);
    float a = g_r[((size_t)b*TT + i0)*HWSZ + hw];
    float c = g_r[((size_t)b*TT + i1)*HWSZ + hw];
    outR[gid] = a + (c - a) * w;
}

// ---------------------------------------------------------------------------
extern "C" void kernel_launch(void* const* d_in, const int* in_sizes, int n_in,
                              void* d_out, int out_size) {
    const float* x     = (const float*)d_in[0];
    const int*   coord = (const int*)  d_in[1];
    const float* Wf    = (const float*)d_in[2];
    const float* bf    = (const float*)d_in[3];
    const float* Wr    = (const float*)d_in[4];
    const float* br    = (const float*)d_in[5];
    const float* W1    = (const float*)d_in[6];
    const float* b1    = (const float*)d_in[7];
    const float* gamma = (const float*)d_in[8];
    const float* beta  = (const float*)d_in[9];
    const float* W2    = (const float*)d_in[10];
    const float* b2    = (const float*)d_in[11];

    float* out  = (float*)d_out;                 // [B,CH,L]   = 6,553,600 floats
    float* outR = out + (size_t)BB*CHN*LL;       // [B,1,FT,H,W] = 3,276,800 floats

    k_prep<<<1, 512>>>(W1, b1, Wf, bf);
    k_r<<<(BB*TT*HWSZ)/256, 256>>>(x, Wr, br);
    k_gather<<<(BB*CC*TT*NN)/256, 256>>>(x, coord);
    k_h<<<NBLK_H, 512>>>();
    k_redstats<<<32, 256>>>();
    k_out<<<BL/256, 256>>>(gamma, beta, W2, b2, out);
    k_result<<<(BB*FT*HWSZ)/256, 256>>>(outR);
}